// round 11
// baseline (speedup 1.0000x reference)
#include <cuda_runtime.h>
#include <math.h>
#include <stdint.h>
#include <stddef.h>

// ============================================================================
// NoisyTopkRouter: fused bf16x3 (Ootomo) mma.sync GEMM + epilogue.
//   a = a1+a2+a3 (bf16 chunks, exact 24-bit split), same for b.
//   main acc:  a1*b1
//   corr acc:  a1*b2 + a2*b1 (2^-8) + a1*b3 + a2*b2 + a3*b1 (2^-16)
// R11 = R10 + cp.async double-buffered B: R10's produce phase exposed
// ~250-600cyc of synchronous B LDG latency inside the barrier window with
// zero MMAs in flight (tensor pipe 47% across R7-R10). B is pre-split in
// gmem -> cp.async streams chunk s+1 into the alternate B buffer under the
// MMAs of chunk s. A stays single-buffered (split via regs, ~150cyc).
// Output layout (validated): [route_p BS*E | ix-as-float BS*K | full_p BS*E]
// ============================================================================

#define E_FIX 64
#define NN    128         // outputs per token
#define MROWS 128         // tokens per CTA
#define KC    32          // K floats per chunk (= 2 k16 MMA steps)
#define NTHR  512
#define CS    132         // C-dump row stride (floats)

// smem planes: u32-packed bf16 pairs, row stride 20 u32 (80B) -> conflict-free
#define RS        20
#define PLANE_U32 (128 * RS)            // 2560 u32 = 10240 B
#define B_BASE_U32 (3 * PLANE_U32)      // A planes: 7680 u32 = 30720 B
#define BUFB_U32   (3 * PLANE_U32)      // one B buffer: 30720 B
#define SMEM_BYTES ((B_BASE_U32 + 2 * BUFB_U32) * 4)   // 92160 B (C dump reuses)

// pre-split B planes, chunk-major: [chunk][plane][row 128][col 16] u32
__device__ uint32_t g_Bp[32 * 3 * 128 * 16];   // 786 KB

typedef unsigned long long u64;

__device__ __forceinline__ uint32_t cvt2(float vhi, float vlo) {
    uint32_t u;
    asm("cvt.rn.bf16x2.f32 %0, %1, %2;" : "=r"(u) : "f"(vhi), "f"(vlo));
    return u;
}
__device__ __forceinline__ float lo_f(uint32_t u) { return __uint_as_float(u << 16); }
__device__ __forceinline__ float hi_f(uint32_t u) { return __uint_as_float(u & 0xFFFF0000u); }

// exact 3-way bf16 split of a float pair -> 3 packed u32
__device__ __forceinline__ void split3p(float vlo, float vhi,
                                        uint32_t& u1, uint32_t& u2, uint32_t& u3) {
    u1 = cvt2(vhi, vlo);
    float r1l = vlo - lo_f(u1), r1h = vhi - hi_f(u1);
    u2 = cvt2(r1h, r1l);
    float r2l = r1l - lo_f(u2), r2h = r1h - hi_f(u2);
    u3 = cvt2(r2h, r2l);
}

__device__ __forceinline__ void ldsm4(uint32_t* r, uint32_t addr) {
    asm volatile("ldmatrix.sync.aligned.m8n8.x4.shared.b16 {%0,%1,%2,%3}, [%4];"
                 : "=r"(r[0]), "=r"(r[1]), "=r"(r[2]), "=r"(r[3]) : "r"(addr));
}
__device__ __forceinline__ void mma_bf16(float* d, const uint32_t* a, const uint32_t* b) {
    asm("mma.sync.aligned.m16n8k16.row.col.f32.bf16.bf16.f32 "
        "{%0,%1,%2,%3}, {%4,%5,%6,%7}, {%8,%9}, {%0,%1,%2,%3};"
        : "+f"(d[0]), "+f"(d[1]), "+f"(d[2]), "+f"(d[3])
        : "r"(a[0]), "r"(a[1]), "r"(a[2]), "r"(a[3]), "r"(b[0]), "r"(b[1]));
}
__device__ __forceinline__ void cp_async16(uint32_t dst, const void* src) {
    asm volatile("cp.async.cg.shared.global [%0], [%1], 16;"
                 :: "r"(dst), "l"(src) : "memory");
}
#define CP_COMMIT() asm volatile("cp.async.commit_group;" ::: "memory")
#define CP_WAIT0()  asm volatile("cp.async.wait_group 0;" ::: "memory")

__device__ __forceinline__ float softplus_f(float x) {
    return fmaxf(x, 0.0f) + log1pf(expf(-fabsf(x)));
}

// ---------------- pre-pass: split W rows into g_Bp planes -------------------
__global__ void __launch_bounds__(512)
bsplit_kernel(const float* __restrict__ Wl, const float* __restrict__ Wn, int D) {
    int idx = blockIdx.x * 512 + threadIdx.x;      // 0..65535 : (row, kpair)
    int row = idx >> 9;                            // 0..127
    int kp  = idx & 511;                           // pair index, k = 2*kp
    const float* W = (row < E_FIX) ? (Wl + (size_t)row * D)
                                   : (Wn + (size_t)(row - E_FIX) * D);
    float v0 = W[2 * kp], v1 = W[2 * kp + 1];
    uint32_t u1, u2, u3;
    split3p(v0, v1, u1, u2, u3);
    int chunk = kp >> 4, col = kp & 15;
    uint32_t* dst = g_Bp + (size_t)chunk * 6144 + row * 16 + col;
    dst[0]    = u1;
    dst[2048] = u2;
    dst[4096] = u3;
}

// ---------------- fused main kernel -----------------------------------------
__global__ void __launch_bounds__(NTHR)
router_fused(const float* __restrict__ h,
             const float* __restrict__ bl,
             const float* __restrict__ bn,
             const float* __restrict__ noise,
             float* __restrict__ out,
             int D, int BS, int K)
{
    extern __shared__ float sf[];
    uint32_t* su = (uint32_t*)sf;
    uint32_t smb;
    asm("{ .reg .u64 t; cvta.to.shared.u64 t, %1; cvt.u32.u64 %0, t; }" : "=r"(smb) : "l"(sf));

    const int tid  = threadIdx.x;
    const int wid  = tid >> 5;
    const int lane = tid & 31;
    const int g    = lane >> 2;
    const int t    = lane & 3;
    const int tokBase = blockIdx.x * MROWS;
    const int mbW = (wid & 3) * 32;      // warp m32 block
    const int nhW = (wid >> 2) * 32;     // warp n32 block

    // ldmatrix per-lane offsets (bytes within a plane) — validated R7 mapping
    const int ti = lane >> 3;
    const int a_off = (((ti & 1) * 8) + (lane & 7)) * 80 + ((ti >> 1) * 16);
    const int b_off = (((ti >> 1) * 8) + (lane & 7)) * 80 + ((ti & 1) * 16);

    // ---- producer assignments ----
    const int arow = tid >> 2, akq = tid & 3;
    const float* aptr = h + (size_t)(tokBase + arow) * D + akq * 8;
    uint32_t* a_sts = su + arow * RS + akq * 4;
    // B: 3 x 16B cp.async per thread; flat uint4 idx f4 = tid + j*512
    uint32_t b_dst[3];                   // byte addr in buffer 0
#pragma unroll
    for (int j = 0; j < 3; ++j) {
        int f = (tid + j * 512) * 4;
        int pl = f >> 11, rem = f & 2047;
        b_dst[j] = smb + (B_BASE_U32 + pl * PLANE_U32 + (rem >> 4) * RS + (rem & 15)) * 4;
    }

    float4 ra0, ra1;

    // ---- prologue: chunk 0 (B via cp.async into buffer 0) ----
    ra0 = *(const float4*)(aptr + 0);
    ra1 = *(const float4*)(aptr + 4);
#pragma unroll
    for (int j = 0; j < 3; ++j)
        cp_async16(b_dst[j], (const char*)g_Bp + (size_t)(tid + j * 512) * 16);
    CP_COMMIT();
    {
        uint32_t p1[4], p2[4], p3[4];
        split3p(ra0.x, ra0.y, p1[0], p2[0], p3[0]);
        split3p(ra0.z, ra0.w, p1[1], p2[1], p3[1]);
        split3p(ra1.x, ra1.y, p1[2], p2[2], p3[2]);
        split3p(ra1.z, ra1.w, p1[3], p2[3], p3[3]);
        *(uint4*)(a_sts + 0 * PLANE_U32) = make_uint4(p1[0], p1[1], p1[2], p1[3]);
        *(uint4*)(a_sts + 1 * PLANE_U32) = make_uint4(p2[0], p2[1], p2[2], p2[3]);
        *(uint4*)(a_sts + 2 * PLANE_U32) = make_uint4(p3[0], p3[1], p3[2], p3[3]);
    }
    CP_WAIT0();
    __syncthreads();

    float accM[2][4][4], accC[2][4][4];
#pragma unroll
    for (int mt = 0; mt < 2; ++mt)
#pragma unroll
        for (int nt = 0; nt < 4; ++nt)
#pragma unroll
            for (int j = 0; j < 4; ++j) { accM[mt][nt][j] = 0.f; accC[mt][nt][j] = 0.f; }

    const int NCH = D / KC;   // 32
    for (int s = 0; s < NCH; ++s) {
        const bool more = (s + 1) < NCH;
        if (more) {
            // stream B(s+1) into alternate buffer under this chunk's MMAs;
            // that buffer's readers finished at chunk s-1 (pre-barrier).
            const char* bsrc = (const char*)(g_Bp + (size_t)(s + 1) * 6144);
            const uint32_t boff = ((s + 1) & 1) * (BUFB_U32 * 4);
#pragma unroll
            for (int j = 0; j < 3; ++j)
                cp_async16(b_dst[j] + boff, bsrc + (size_t)(tid + j * 512) * 16);
            CP_COMMIT();
            const int off = (s + 1) * KC;        // A reg prefetch (8 regs)
            ra0 = *(const float4*)(aptr + off);
            ra1 = *(const float4*)(aptr + off + 4);
        }

        // ---- consume: 2 k16 steps, term-major MMA order ----
        const uint32_t bbase = smb + (B_BASE_U32 + (s & 1) * BUFB_U32) * 4;
#pragma unroll
        for (int kb = 0; kb < 2; ++kb) {
            uint32_t aa[3][2][4];
#pragma unroll
            for (int p = 0; p < 3; ++p)
#pragma unroll
                for (int mt = 0; mt < 2; ++mt)
                    ldsm4(aa[p][mt],
                          smb + p * 10240 + (mbW + mt * 16) * 80 + kb * 32 + a_off);
            uint32_t bb[3][2][4];
#pragma unroll
            for (int p = 0; p < 3; ++p)
#pragma unroll
                for (int bt = 0; bt < 2; ++bt)
                    ldsm4(bb[p][bt],
                          bbase + p * 10240 + (nhW + bt * 16) * 80 + kb * 32 + b_off);

#define EMIT_TERM(ACC, PA, PB)                                           \
            _Pragma("unroll")                                            \
            for (int mt = 0; mt < 2; ++mt)                               \
                _Pragma("unroll")                                        \
                for (int bt = 0; bt < 2; ++bt)                           \
                    _Pragma("unroll")                                    \
                    for (int j = 0; j < 2; ++j)                          \
                        mma_bf16(ACC[mt][bt * 2 + j], aa[PA][mt],        \
                                 bb[PB][bt] + 2 * j);
            EMIT_TERM(accM, 0, 0)
            EMIT_TERM(accC, 0, 1)
            EMIT_TERM(accC, 1, 0)
            EMIT_TERM(accC, 0, 2)
            EMIT_TERM(accC, 1, 1)
            EMIT_TERM(accC, 2, 0)
#undef EMIT_TERM
        }
        __syncthreads();                 // A-plane readers done

        // ---- short produce: A split/STS only; B already in flight ----
        if (more) {
            uint32_t p1[4], p2[4], p3[4];
            split3p(ra0.x, ra0.y, p1[0], p2[0], p3[0]);
            split3p(ra0.z, ra0.w, p1[1], p2[1], p3[1]);
            split3p(ra1.x, ra1.y, p1[2], p2[2], p3[2]);
            split3p(ra1.z, ra1.w, p1[3], p2[3], p3[3]);
            *(uint4*)(a_sts + 0 * PLANE_U32) = make_uint4(p1[0], p1[1], p1[2], p1[3]);
            *(uint4*)(a_sts + 1 * PLANE_U32) = make_uint4(p2[0], p2[1], p2[2], p2[3]);
            *(uint4*)(a_sts + 2 * PLANE_U32) = make_uint4(p3[0], p3[1], p3[2], p3[3]);
            CP_WAIT0();                  // B(s+1) landed
            __syncthreads();             // publish A planes + B buffer
        }
    }

    // ---- merge + dump C to smem (reuses plane region) ----
#pragma unroll
    for (int mt = 0; mt < 2; ++mt)
#pragma unroll
        for (int nt = 0; nt < 4; ++nt) {
            const int r0 = mbW + mt * 16 + g;
            const int c  = nhW + nt * 8 + 2 * t;
            *(float2*)&sf[r0 * CS + c] =
                make_float2(accM[mt][nt][0] + accC[mt][nt][0],
                            accM[mt][nt][1] + accC[mt][nt][1]);
            *(float2*)&sf[(r0 + 8) * CS + c] =
                make_float2(accM[mt][nt][2] + accC[mt][nt][2],
                            accM[mt][nt][3] + accC[mt][nt][3]);
        }
    __syncthreads();

    // ---- epilogue: thread tid<128 handles token tokBase+tid (validated) ----
    if (tid < MROWS) {
        const int tok = tokBase + tid;
        const float* pre = sf + tid * CS;
        const float* nzr = noise + (size_t)tok * E_FIX;

        float noisy[E_FIX];
#pragma unroll
        for (int q = 0; q < E_FIX / 4; ++q) {
            float4 lg = *(const float4*)(pre + 4 * q);
            float4 np = *(const float4*)(pre + E_FIX + 4 * q);
            float4 nv = *(const float4*)(nzr + 4 * q);
            float4 b0 = *(const float4*)(bl + 4 * q);
            float4 b1 = *(const float4*)(bn + 4 * q);
            noisy[4*q+0] = lg.x + b0.x + nv.x * softplus_f(np.x + b1.x);
            noisy[4*q+1] = lg.y + b0.y + nv.y * softplus_f(np.y + b1.y);
            noisy[4*q+2] = lg.z + b0.z + nv.z * softplus_f(np.z + b1.z);
            noisy[4*q+3] = lg.w + b0.w + nv.w * softplus_f(np.w + b1.w);
        }

        float m = noisy[0];
#pragma unroll
        for (int e = 1; e < E_FIX; ++e) m = fmaxf(m, noisy[e]);

        int kidx[8]; float kval[8];
        u64 chosen = 0ull;
        for (int j = 0; j < K; ++j) {
            float best = -INFINITY; int bi = 0;
#pragma unroll
            for (int e = 0; e < E_FIX; ++e) {
                bool ok = (((chosen >> e) & 1ull) == 0ull) && (noisy[e] > best);
                best = ok ? noisy[e] : best;
                bi   = ok ? e : bi;
            }
            kidx[j] = bi; kval[j] = best;
            chosen |= (1ull << bi);
        }

        float sum = 0.0f;
#pragma unroll
        for (int e = 0; e < E_FIX; ++e) { float x = expf(noisy[e] - m); noisy[e] = x; sum += x; }
        const float inv = 1.0f / sum;

        float* route = out + (size_t)tok * E_FIX;
        float* ixo   = out + (size_t)BS * E_FIX + (size_t)tok * K;
        float* fullp = out + (size_t)BS * (E_FIX + K) + (size_t)tok * E_FIX;
#pragma unroll
        for (int q = 0; q < 16; ++q) *(float4*)(route + 4 * q) = make_float4(0.f, 0.f, 0.f, 0.f);
#pragma unroll
        for (int q = 0; q < 16; ++q)
            *(float4*)(fullp + 4 * q) = make_float4(noisy[4*q+0] * inv, noisy[4*q+1] * inv,
                                                    noisy[4*q+2] * inv, noisy[4*q+3] * inv);
        const float rm = kval[0];
        float rs = 0.0f, rv[8];
        for (int j = 0; j < K; ++j) { rv[j] = expf(kval[j] - rm); rs += rv[j]; }
        const float rinv = 1.0f / rs;
        for (int j = 0; j < K; ++j) { route[kidx[j]] = rv[j] * rinv; ixo[j] = (float)kidx[j]; }
    }
}

// ----------------------------------------------------------------------------
// Inputs (metadata order): h, Wl, bl, Wn, bn, noise, [top_k]
// ----------------------------------------------------------------------------
extern "C" void kernel_launch(void* const* d_in, const int* in_sizes, int n_in,
                              void* d_out, int out_size) {
    const float* h  = (const float*)d_in[0];
    const float* Wl = (const float*)d_in[1];
    const float* bl = (const float*)d_in[2];
    const float* Wn = (const float*)d_in[3];
    const float* bn = (const float*)d_in[4];
    const float* nz = (const float*)d_in[5];

    const int E = in_sizes[2];                     // 64
    const int D = in_sizes[1] / E;                 // 1024
    const long long BSE = (long long)in_sizes[5];  // B*S*E
    const int BS = (int)(BSE / E);                 // 32768

    int K = (int)(((long long)out_size - 2LL * BSE) / (long long)BS);
    if (K < 1 || K > 8) K = 2;

    bsplit_kernel<<<128, 512>>>(Wl, Wn, D);
    cudaFuncSetAttribute(router_fused, cudaFuncAttributeMaxDynamicSharedMemorySize, SMEM_BYTES);
    router_fused<<<BS / MROWS, NTHR, SMEM_BYTES>>>(h, bl, bn, nz, (float*)d_out, D, BS, K);
}

// round 12
// speedup vs baseline: 1.4525x; 1.4525x over previous
#include <cuda_runtime.h>
#include <math.h>
#include <stdint.h>
#include <stddef.h>

// ============================================================================
// NoisyTopkRouter: fused fp16x2 (3-term Dekker) mma.sync GEMM + epilogue.
//   R7-R11 established: wall time == mma.m16n8k16 structural floor (~15cyc/
//   MMA/SMSP; tensor 47% duty across 4 different schedules). Only lever left
//   is MMA count -> switch bf16x3/6-term (12.6M MMAs) to fp16x2/3-term
//   (6.3M MMAs). fp16 2-way split captures 22 mantissa bits; error ~2^-23|ab|
//   per product ~1e-7/logit => same zero-flip grade as the passing kernel.
//   DENORMAL GUARD: operands pre-scaled by 2^12 before splitting so all
//   split residuals stay fp16-normal (W~0.02 residuals would otherwise sit
//   on the 6e-8 denormal grid => 1e-5 logit noise, the R5 failure mode).
//   C is unscaled by exact 2^-24 at merge.
//   main acc:  ah*bh ; corr acc: ah*bl + al*bh  (dropped al*bl ~2^-22)
// Output layout (validated): [route_p BS*E | ix-as-float BS*K | full_p BS*E]
// ============================================================================

#define E_FIX 64
#define NN    128         // outputs per token
#define MROWS 128         // tokens per CTA
#define KC    32          // K floats per chunk (= 2 k16 MMA steps)
#define NTHR  512
#define CS    132         // C-dump row stride (floats)
#define SCALE   4096.0f   // 2^12 operand pre-scale
#define INV_SC  (1.0f / 16777216.0f)   // 2^-24, exact

// smem planes: u32-packed fp16 pairs, row stride 20 u32 (80B) -> conflict-free
#define RS        20
#define PLANE_U32 (128 * RS)            // 2560 u32 = 10240 B
#define B_BASE_B  (2 * PLANE_U32 * 4)   // A: 2 planes = 20480 B
#define SMEM_BYTES 69632                // max(planes 40960, C dump 128*132*4)

// pre-split B planes, chunk-major: [chunk][plane 2][row 128][col 16] u32
__device__ uint32_t g_Bp[32 * 2 * 128 * 16];   // 512 KB

typedef unsigned long long u64;

// pack two floats -> f16x2 (args: hi half, lo half)
__device__ __forceinline__ uint32_t cvt2h(float vhi, float vlo) {
    uint32_t u;
    asm("cvt.rn.f16x2.f32 %0, %1, %2;" : "=r"(u) : "f"(vhi), "f"(vlo));
    return u;
}
__device__ __forceinline__ void unpack2h(uint32_t u, float& flo, float& fhi) {
    asm("{ .reg .b16 l, h;\n"
        "  mov.b32 {l, h}, %2;\n"
        "  cvt.f32.f16 %0, l;\n"
        "  cvt.f32.f16 %1, h; }"
        : "=f"(flo), "=f"(fhi) : "r"(u));
}
// 2-way fp16 split of a float pair (callers pre-scale so residuals are normal)
__device__ __forceinline__ void split2h(float vlo, float vhi,
                                        uint32_t& u1, uint32_t& u2) {
    u1 = cvt2h(vhi, vlo);
    float r1l, r1h;
    unpack2h(u1, r1l, r1h);
    u2 = cvt2h(vhi - r1h, vlo - r1l);
}

__device__ __forceinline__ void ldsm4(uint32_t* r, uint32_t addr) {
    asm volatile("ldmatrix.sync.aligned.m8n8.x4.shared.b16 {%0,%1,%2,%3}, [%4];"
                 : "=r"(r[0]), "=r"(r[1]), "=r"(r[2]), "=r"(r[3]) : "r"(addr));
}
__device__ __forceinline__ void mma_f16(float* d, const uint32_t* a, const uint32_t* b) {
    asm("mma.sync.aligned.m16n8k16.row.col.f32.f16.f16.f32 "
        "{%0,%1,%2,%3}, {%4,%5,%6,%7}, {%8,%9}, {%0,%1,%2,%3};"
        : "+f"(d[0]), "+f"(d[1]), "+f"(d[2]), "+f"(d[3])
        : "r"(a[0]), "r"(a[1]), "r"(a[2]), "r"(a[3]), "r"(b[0]), "r"(b[1]));
}
__device__ __forceinline__ float softplus_f(float x) {
    return fmaxf(x, 0.0f) + log1pf(expf(-fabsf(x)));
}

// ---------------- pre-pass: scale + split W rows into g_Bp planes ----------
__global__ void __launch_bounds__(512)
bsplit_kernel(const float* __restrict__ Wl, const float* __restrict__ Wn, int D) {
    int idx = blockIdx.x * 512 + threadIdx.x;      // 0..65535 : (row, kpair)
    int row = idx >> 9;                            // 0..127
    int kp  = idx & 511;                           // pair index, k = 2*kp
    const float* W = (row < E_FIX) ? (Wl + (size_t)row * D)
                                   : (Wn + (size_t)(row - E_FIX) * D);
    float v0 = W[2 * kp] * SCALE, v1 = W[2 * kp + 1] * SCALE;
    uint32_t u1, u2;
    split2h(v0, v1, u1, u2);
    int chunk = kp >> 4, col = kp & 15;
    uint32_t* dst = g_Bp + (size_t)chunk * 4096 + row * 16 + col;
    dst[0]    = u1;
    dst[2048] = u2;
}

// ---------------- fused main kernel -----------------------------------------
__global__ void __launch_bounds__(NTHR)
router_fused(const float* __restrict__ h,
             const float* __restrict__ bl,
             const float* __restrict__ bn,
             const float* __restrict__ noise,
             float* __restrict__ out,
             int D, int BS, int K)
{
    extern __shared__ float sf[];
    uint32_t* su = (uint32_t*)sf;
    uint32_t smb;
    asm("{ .reg .u64 t; cvta.to.shared.u64 t, %1; cvt.u32.u64 %0, t; }" : "=r"(smb) : "l"(sf));

    const int tid  = threadIdx.x;
    const int wid  = tid >> 5;
    const int lane = tid & 31;
    const int g    = lane >> 2;
    const int t    = lane & 3;
    const int tokBase = blockIdx.x * MROWS;
    const int mbW = (wid & 3) * 32;      // warp m32 block
    const int nhW = (wid >> 2) * 32;     // warp n32 block

    // ldmatrix per-lane offsets (bytes within a plane) — validated R7 mapping
    const int ti = lane >> 3;
    const int a_off = (((ti & 1) * 8) + (lane & 7)) * 80 + ((ti >> 1) * 16);
    const int b_off = (((ti >> 1) * 8) + (lane & 7)) * 80 + ((ti & 1) * 16);

    // ---- producer assignments ----
    const int arow = tid >> 2, akq = tid & 3;
    const float* aptr = h + (size_t)(tokBase + arow) * D + akq * 8;
    uint32_t* a_sts = su + arow * RS + akq * 4;
    // B: 2 uint4 per thread; flat uint4 idx f4 = tid + j*512 -> u32 f = 4*f4
    int b_pl[2], b_su[2];
#pragma unroll
    for (int j = 0; j < 2; ++j) {
        int f = (tid + j * 512) * 4;
        b_pl[j] = f >> 11;
        int rem = f & 2047;
        b_su[j] = (rem >> 4) * RS + (rem & 15);
    }
    uint32_t* b_sts_base = su + (B_BASE_B / 4);

    float4 ra0, ra1;

    // ---- prologue: chunk 0 ----
    ra0 = *(const float4*)(aptr + 0);
    ra1 = *(const float4*)(aptr + 4);
    {
        uint32_t p1[4], p2[4];
        split2h(ra0.x * SCALE, ra0.y * SCALE, p1[0], p2[0]);
        split2h(ra0.z * SCALE, ra0.w * SCALE, p1[1], p2[1]);
        split2h(ra1.x * SCALE, ra1.y * SCALE, p1[2], p2[2]);
        split2h(ra1.z * SCALE, ra1.w * SCALE, p1[3], p2[3]);
        *(uint4*)(a_sts + 0 * PLANE_U32) = make_uint4(p1[0], p1[1], p1[2], p1[3]);
        *(uint4*)(a_sts + 1 * PLANE_U32) = make_uint4(p2[0], p2[1], p2[2], p2[3]);
        const uint4* bp = (const uint4*)g_Bp;
#pragma unroll
        for (int j = 0; j < 2; ++j) {
            uint4 v = bp[tid + j * 512];
            *(uint4*)(b_sts_base + b_pl[j] * PLANE_U32 + b_su[j]) = v;
        }
    }
    __syncthreads();

    float accM[2][4][4], accC[2][4][4];
#pragma unroll
    for (int mt = 0; mt < 2; ++mt)
#pragma unroll
        for (int nt = 0; nt < 4; ++nt)
#pragma unroll
            for (int j = 0; j < 4; ++j) { accM[mt][nt][j] = 0.f; accC[mt][nt][j] = 0.f; }

    const int NCH = D / KC;   // 32
    for (int s = 0; s < NCH; ++s) {
        const bool more = (s + 1) < NCH;
        if (more) {                       // A reg prefetch (8 regs)
            const int off = (s + 1) * KC;
            ra0 = *(const float4*)(aptr + off);
            ra1 = *(const float4*)(aptr + off + 4);
        }

        // ---- consume: 2 k16 steps, 3-term fp16 split ----
#pragma unroll
        for (int kb = 0; kb < 2; ++kb) {
            uint32_t aa[2][2][4];
#pragma unroll
            for (int p = 0; p < 2; ++p)
#pragma unroll
                for (int mt = 0; mt < 2; ++mt)
                    ldsm4(aa[p][mt],
                          smb + p * 10240 + (mbW + mt * 16) * 80 + kb * 32 + a_off);
            uint32_t bb[2][2][4];
#pragma unroll
            for (int p = 0; p < 2; ++p)
#pragma unroll
                for (int bt = 0; bt < 2; ++bt)
                    ldsm4(bb[p][bt],
                          smb + B_BASE_B + p * 10240 + (nhW + bt * 16) * 80 + kb * 32 + b_off);

#define EMIT_TERM(ACC, PA, PB)                                           \
            _Pragma("unroll")                                            \
            for (int mt = 0; mt < 2; ++mt)                               \
                _Pragma("unroll")                                        \
                for (int bt = 0; bt < 2; ++bt)                           \
                    _Pragma("unroll")                                    \
                    for (int j = 0; j < 2; ++j)                          \
                        mma_f16(ACC[mt][bt * 2 + j], aa[PA][mt],         \
                                bb[PB][bt] + 2 * j);
            EMIT_TERM(accM, 0, 0)
            EMIT_TERM(accC, 0, 1)
            EMIT_TERM(accC, 1, 0)
#undef EMIT_TERM
        }
        __syncthreads();

        // ---- produce chunk s+1: A split from regs, B direct L2->smem ----
        if (more) {
            uint32_t p1[4], p2[4];
            split2h(ra0.x * SCALE, ra0.y * SCALE, p1[0], p2[0]);
            split2h(ra0.z * SCALE, ra0.w * SCALE, p1[1], p2[1]);
            split2h(ra1.x * SCALE, ra1.y * SCALE, p1[2], p2[2]);
            split2h(ra1.z * SCALE, ra1.w * SCALE, p1[3], p2[3]);
            *(uint4*)(a_sts + 0 * PLANE_U32) = make_uint4(p1[0], p1[1], p1[2], p1[3]);
            *(uint4*)(a_sts + 1 * PLANE_U32) = make_uint4(p2[0], p2[1], p2[2], p2[3]);
            const uint4* bp = (const uint4*)(g_Bp + (size_t)(s + 1) * 4096);
#pragma unroll
            for (int j = 0; j < 2; ++j) {
                uint4 v = bp[tid + j * 512];
                *(uint4*)(b_sts_base + b_pl[j] * PLANE_U32 + b_su[j]) = v;
            }
            __syncthreads();
        }
    }

    // ---- merge + unscale (exact 2^-24) + dump C to smem ----
#pragma unroll
    for (int mt = 0; mt < 2; ++mt)
#pragma unroll
        for (int nt = 0; nt < 4; ++nt) {
            const int r0 = mbW + mt * 16 + g;
            const int c  = nhW + nt * 8 + 2 * t;
            *(float2*)&sf[r0 * CS + c] =
                make_float2((accM[mt][nt][0] + accC[mt][nt][0]) * INV_SC,
                            (accM[mt][nt][1] + accC[mt][nt][1]) * INV_SC);
            *(float2*)&sf[(r0 + 8) * CS + c] =
                make_float2((accM[mt][nt][2] + accC[mt][nt][2]) * INV_SC,
                            (accM[mt][nt][3] + accC[mt][nt][3]) * INV_SC);
        }
    __syncthreads();

    // ---- epilogue: thread tid<128 handles token tokBase+tid (validated) ----
    if (tid < MROWS) {
        const int tok = tokBase + tid;
        const float* pre = sf + tid * CS;
        const float* nzr = noise + (size_t)tok * E_FIX;

        float noisy[E_FIX];
#pragma unroll
        for (int q = 0; q < E_FIX / 4; ++q) {
            float4 lg = *(const float4*)(pre + 4 * q);
            float4 np = *(const float4*)(pre + E_FIX + 4 * q);
            float4 nv = *(const float4*)(nzr + 4 * q);
            float4 b0 = *(const float4*)(bl + 4 * q);
            float4 b1 = *(const float4*)(bn + 4 * q);
            noisy[4*q+0] = lg.x + b0.x + nv.x * softplus_f(np.x + b1.x);
            noisy[4*q+1] = lg.y + b0.y + nv.y * softplus_f(np.y + b1.y);
            noisy[4*q+2] = lg.z + b0.z + nv.z * softplus_f(np.z + b1.z);
            noisy[4*q+3] = lg.w + b0.w + nv.w * softplus_f(np.w + b1.w);
        }

        float m = noisy[0];
#pragma unroll
        for (int e = 1; e < E_FIX; ++e) m = fmaxf(m, noisy[e]);

        int kidx[8]; float kval[8];
        u64 chosen = 0ull;
        for (int j = 0; j < K; ++j) {
            float best = -INFINITY; int bi = 0;
#pragma unroll
            for (int e = 0; e < E_FIX; ++e) {
                bool ok = (((chosen >> e) & 1ull) == 0ull) && (noisy[e] > best);
                best = ok ? noisy[e] : best;
                bi   = ok ? e : bi;
            }
            kidx[j] = bi; kval[j] = best;
            chosen |= (1ull << bi);
        }

        float sum = 0.0f;
#pragma unroll
        for (int e = 0; e < E_FIX; ++e) { float x = expf(noisy[e] - m); noisy[e] = x; sum += x; }
        const float inv = 1.0f / sum;

        float* route = out + (size_t)tok * E_FIX;
        float* ixo   = out + (size_t)BS * E_FIX + (size_t)tok * K;
        float* fullp = out + (size_t)BS * (E_FIX + K) + (size_t)tok * E_FIX;
#pragma unroll
        for (int q = 0; q < 16; ++q) *(float4*)(route + 4 * q) = make_float4(0.f, 0.f, 0.f, 0.f);
#pragma unroll
        for (int q = 0; q < 16; ++q)
            *(float4*)(fullp + 4 * q) = make_float4(noisy[4*q+0] * inv, noisy[4*q+1] * inv,
                                                    noisy[4*q+2] * inv, noisy[4*q+3] * inv);
        const float rm = kval[0];
        float rs = 0.0f, rv[8];
        for (int j = 0; j < K; ++j) { rv[j] = expf(kval[j] - rm); rs += rv[j]; }
        const float rinv = 1.0f / rs;
        for (int j = 0; j < K; ++j) { route[kidx[j]] = rv[j] * rinv; ixo[j] = (float)kidx[j]; }
    }
}

// ----------------------------------------------------------------------------
// Inputs (metadata order): h, Wl, bl, Wn, bn, noise, [top_k]
// ----------------------------------------------------------------------------
extern "C" void kernel_launch(void* const* d_in, const int* in_sizes, int n_in,
                              void* d_out, int out_size) {
    const float* h  = (const float*)d_in[0];
    const float* Wl = (const float*)d_in[1];
    const float* bl = (const float*)d_in[2];
    const float* Wn = (const float*)d_in[3];
    const float* bn = (const float*)d_in[4];
    const float* nz = (const float*)d_in[5];

    const int E = in_sizes[2];                     // 64
    const int D = in_sizes[1] / E;                 // 1024
    const long long BSE = (long long)in_sizes[5];  // B*S*E
    const int BS = (int)(BSE / E);                 // 32768

    int K = (int)(((long long)out_size - 2LL * BSE) / (long long)BS);
    if (K < 1 || K > 8) K = 2;

    bsplit_kernel<<<128, 512>>>(Wl, Wn, D);
    cudaFuncSetAttribute(router_fused, cudaFuncAttributeMaxDynamicSharedMemorySize, SMEM_BYTES);
    router_fused<<<BS / MROWS, NTHR, SMEM_BYTES>>>(h, bl, bn, nz, (float*)d_out, D, BS, K);
}

// round 13
// speedup vs baseline: 1.7142x; 1.1802x over previous
#include <cuda_runtime.h>
#include <math.h>
#include <stdint.h>
#include <stddef.h>

// ============================================================================
// NoisyTopkRouter: fused fp16x2 (3-term Dekker) mma.sync GEMM + epilogue.
//   R12 (123.8us) proved the fp16x2 numerics (rel_err 1.38e-6) and showed
//   tensor duty at 32.5% -> overhead-bound again: ~600cyc synchronous B LDG
//   + 2 barriers per chunk dominate. R13 = R12 math + full double-buffering:
//   cp.async streams B(s+1) under chunk s MMAs (R11 machinery, now in its
//   valid regime), A(s+1) split lands in the alternate buffer, ONE barrier
//   per chunk.
//   DENORMAL GUARD: operands pre-scaled by 2^12 (residuals stay fp16-normal);
//   C unscaled by exact 2^-24 at merge.
//   main acc: ah*bh ; corr acc: ah*bl + al*bh
// Output layout (validated): [route_p BS*E | ix-as-float BS*K | full_p BS*E]
// ============================================================================

#define E_FIX 64
#define NN    128         // outputs per token
#define MROWS 128         // tokens per CTA
#define KC    32          // K floats per chunk (= 2 k16 MMA steps)
#define NTHR  512
#define CS    132         // C-dump row stride (floats)
#define SCALE   4096.0f   // 2^12 operand pre-scale
#define INV_SC  (1.0f / 16777216.0f)   // 2^-24, exact

// smem planes: u32-packed fp16 pairs, row stride 20 u32 (80B) -> conflict-free
#define RS        20
#define PLANE_U32 (128 * RS)            // 2560 u32 = 10240 B
#define PLANE_B   (PLANE_U32 * 4)
#define ABUF_B    (2 * PLANE_B)         // 20480 B per A buffer (2 planes)
#define B_BASE_B  (2 * ABUF_B)          // 40960: B buffers start
#define BBUF_B    (2 * PLANE_B)         // 20480 B per B buffer
#define SMEM_BYTES (B_BASE_B + 2 * BBUF_B)   // 81920 B (C dump 67584 reuses)

// pre-split B planes, chunk-major: [chunk][plane 2][row 128][col 16] u32
__device__ uint32_t g_Bp[32 * 2 * 128 * 16];   // 512 KB

typedef unsigned long long u64;

// pack two floats -> f16x2 (args: hi half, lo half)
__device__ __forceinline__ uint32_t cvt2h(float vhi, float vlo) {
    uint32_t u;
    asm("cvt.rn.f16x2.f32 %0, %1, %2;" : "=r"(u) : "f"(vhi), "f"(vlo));
    return u;
}
__device__ __forceinline__ void unpack2h(uint32_t u, float& flo, float& fhi) {
    asm("{ .reg .b16 l, h;\n"
        "  mov.b32 {l, h}, %2;\n"
        "  cvt.f32.f16 %0, l;\n"
        "  cvt.f32.f16 %1, h; }"
        : "=f"(flo), "=f"(fhi) : "r"(u));
}
// 2-way fp16 split of a float pair (callers pre-scale so residuals are normal)
__device__ __forceinline__ void split2h(float vlo, float vhi,
                                        uint32_t& u1, uint32_t& u2) {
    u1 = cvt2h(vhi, vlo);
    float r1l, r1h;
    unpack2h(u1, r1l, r1h);
    u2 = cvt2h(vhi - r1h, vlo - r1l);
}

__device__ __forceinline__ void ldsm4(uint32_t* r, uint32_t addr) {
    asm volatile("ldmatrix.sync.aligned.m8n8.x4.shared.b16 {%0,%1,%2,%3}, [%4];"
                 : "=r"(r[0]), "=r"(r[1]), "=r"(r[2]), "=r"(r[3]) : "r"(addr));
}
__device__ __forceinline__ void mma_f16(float* d, const uint32_t* a, const uint32_t* b) {
    asm("mma.sync.aligned.m16n8k16.row.col.f32.f16.f16.f32 "
        "{%0,%1,%2,%3}, {%4,%5,%6,%7}, {%8,%9}, {%0,%1,%2,%3};"
        : "+f"(d[0]), "+f"(d[1]), "+f"(d[2]), "+f"(d[3])
        : "r"(a[0]), "r"(a[1]), "r"(a[2]), "r"(a[3]), "r"(b[0]), "r"(b[1]));
}
__device__ __forceinline__ void cp_async16(uint32_t dst, const void* src) {
    asm volatile("cp.async.cg.shared.global [%0], [%1], 16;"
                 :: "r"(dst), "l"(src) : "memory");
}
#define CP_COMMIT() asm volatile("cp.async.commit_group;" ::: "memory")
#define CP_WAIT0()  asm volatile("cp.async.wait_group 0;" ::: "memory")

__device__ __forceinline__ float softplus_f(float x) {
    return fmaxf(x, 0.0f) + log1pf(expf(-fabsf(x)));
}

// ---------------- pre-pass: scale + split W rows into g_Bp planes ----------
__global__ void __launch_bounds__(512)
bsplit_kernel(const float* __restrict__ Wl, const float* __restrict__ Wn, int D) {
    int idx = blockIdx.x * 512 + threadIdx.x;      // 0..65535 : (row, kpair)
    int row = idx >> 9;                            // 0..127
    int kp  = idx & 511;                           // pair index, k = 2*kp
    const float* W = (row < E_FIX) ? (Wl + (size_t)row * D)
                                   : (Wn + (size_t)(row - E_FIX) * D);
    float v0 = W[2 * kp] * SCALE, v1 = W[2 * kp + 1] * SCALE;
    uint32_t u1, u2;
    split2h(v0, v1, u1, u2);
    int chunk = kp >> 4, col = kp & 15;
    uint32_t* dst = g_Bp + (size_t)chunk * 4096 + row * 16 + col;
    dst[0]    = u1;
    dst[2048] = u2;
}

// ---------------- fused main kernel -----------------------------------------
__global__ void __launch_bounds__(NTHR)
router_fused(const float* __restrict__ h,
             const float* __restrict__ bl,
             const float* __restrict__ bn,
             const float* __restrict__ noise,
             float* __restrict__ out,
             int D, int BS, int K)
{
    extern __shared__ float sf[];
    uint32_t* su = (uint32_t*)sf;
    uint32_t smb;
    asm("{ .reg .u64 t; cvta.to.shared.u64 t, %1; cvt.u32.u64 %0, t; }" : "=r"(smb) : "l"(sf));

    const int tid  = threadIdx.x;
    const int wid  = tid >> 5;
    const int lane = tid & 31;
    const int g    = lane >> 2;
    const int t    = lane & 3;
    const int tokBase = blockIdx.x * MROWS;
    const int mbW = (wid & 3) * 32;      // warp m32 block
    const int nhW = (wid >> 2) * 32;     // warp n32 block

    // ldmatrix per-lane offsets (bytes within a plane) — validated R7 mapping
    const int ti = lane >> 3;
    const int a_off = (((ti & 1) * 8) + (lane & 7)) * 80 + ((ti >> 1) * 16);
    const int b_off = (((ti >> 1) * 8) + (lane & 7)) * 80 + ((ti & 1) * 16);

    // ---- producer assignments ----
    const int arow = tid >> 2, akq = tid & 3;
    const float* aptr = h + (size_t)(tokBase + arow) * D + akq * 8;
    const int a_su = arow * RS + akq * 4;           // u32 idx within a plane
    // B: 2 x 16B cp.async per thread; flat uint4 idx f4 = tid + j*512
    uint32_t b_dst[2];                   // byte addr in B buffer 0
#pragma unroll
    for (int j = 0; j < 2; ++j) {
        int f = (tid + j * 512) * 4;
        int pl = f >> 11, rem = f & 2047;
        b_dst[j] = smb + B_BASE_B + pl * PLANE_B + ((rem >> 4) * RS + (rem & 15)) * 4;
    }

    float4 ra0, ra1;

    // ---- prologue: chunk 0 -> buffers 0 ----
    ra0 = *(const float4*)(aptr + 0);
    ra1 = *(const float4*)(aptr + 4);
#pragma unroll
    for (int j = 0; j < 2; ++j)
        cp_async16(b_dst[j], (const char*)g_Bp + (size_t)(tid + j * 512) * 16);
    CP_COMMIT();
    {
        uint32_t p1[4], p2[4];
        split2h(ra0.x * SCALE, ra0.y * SCALE, p1[0], p2[0]);
        split2h(ra0.z * SCALE, ra0.w * SCALE, p1[1], p2[1]);
        split2h(ra1.x * SCALE, ra1.y * SCALE, p1[2], p2[2]);
        split2h(ra1.z * SCALE, ra1.w * SCALE, p1[3], p2[3]);
        uint32_t* ab = su + a_su;
        *(uint4*)(ab + 0 * PLANE_U32) = make_uint4(p1[0], p1[1], p1[2], p1[3]);
        *(uint4*)(ab + 1 * PLANE_U32) = make_uint4(p2[0], p2[1], p2[2], p2[3]);
    }
    CP_WAIT0();
    __syncthreads();

    float accM[2][4][4], accC[2][4][4];
#pragma unroll
    for (int mt = 0; mt < 2; ++mt)
#pragma unroll
        for (int nt = 0; nt < 4; ++nt)
#pragma unroll
            for (int j = 0; j < 4; ++j) { accM[mt][nt][j] = 0.f; accC[mt][nt][j] = 0.f; }

    const int NCH = D / KC;   // 32
    for (int s = 0; s < NCH; ++s) {
        const bool more = (s + 1) < NCH;
        if (more) {
            // stream B(s+1) into the alternate buffer (readers done at s-1)
            const char* bsrc = (const char*)(g_Bp + (size_t)(s + 1) * 4096);
            const uint32_t boff = ((s + 1) & 1) * BBUF_B;
#pragma unroll
            for (int j = 0; j < 2; ++j)
                cp_async16(b_dst[j] + boff, bsrc + (size_t)(tid + j * 512) * 16);
            CP_COMMIT();
            const int off = (s + 1) * KC;        // A reg prefetch (8 regs)
            ra0 = *(const float4*)(aptr + off);
            ra1 = *(const float4*)(aptr + off + 4);
        }

        // ---- consume buffers s&1: 2 k16 steps, 3-term fp16 split ----
        const uint32_t abase = smb + (s & 1) * ABUF_B;
        const uint32_t bbase = smb + B_BASE_B + (s & 1) * BBUF_B;
#pragma unroll
        for (int kb = 0; kb < 2; ++kb) {
            uint32_t aa[2][2][4];
#pragma unroll
            for (int p = 0; p < 2; ++p)
#pragma unroll
                for (int mt = 0; mt < 2; ++mt)
                    ldsm4(aa[p][mt],
                          abase + p * PLANE_B + (mbW + mt * 16) * 80 + kb * 32 + a_off);
            uint32_t bb[2][2][4];
#pragma unroll
            for (int p = 0; p < 2; ++p)
#pragma unroll
                for (int bt = 0; bt < 2; ++bt)
                    ldsm4(bb[p][bt],
                          bbase + p * PLANE_B + (nhW + bt * 16) * 80 + kb * 32 + b_off);

#define EMIT_TERM(ACC, PA, PB)                                           \
            _Pragma("unroll")                                            \
            for (int mt = 0; mt < 2; ++mt)                               \
                _Pragma("unroll")                                        \
                for (int bt = 0; bt < 2; ++bt)                           \
                    _Pragma("unroll")                                    \
                    for (int j = 0; j < 2; ++j)                          \
                        mma_f16(ACC[mt][bt * 2 + j], aa[PA][mt],         \
                                bb[PB][bt] + 2 * j);
            EMIT_TERM(accM, 0, 0)
            EMIT_TERM(accC, 0, 1)
            EMIT_TERM(accC, 1, 0)
#undef EMIT_TERM
        }

        // ---- produce A(s+1) into the alternate A buffer (readers done s-1) ----
        if (more) {
            uint32_t p1[4], p2[4];
            split2h(ra0.x * SCALE, ra0.y * SCALE, p1[0], p2[0]);
            split2h(ra0.z * SCALE, ra0.w * SCALE, p1[1], p2[1]);
            split2h(ra1.x * SCALE, ra1.y * SCALE, p1[2], p2[2]);
            split2h(ra1.z * SCALE, ra1.w * SCALE, p1[3], p2[3]);
            uint32_t* ab = su + ((s + 1) & 1) * (ABUF_B / 4) + a_su;
            *(uint4*)(ab + 0 * PLANE_U32) = make_uint4(p1[0], p1[1], p1[2], p1[3]);
            *(uint4*)(ab + 1 * PLANE_U32) = make_uint4(p2[0], p2[1], p2[2], p2[3]);
            CP_WAIT0();                  // B(s+1) landed
        }
        __syncthreads();                 // single barrier: publish s+1, retire s
    }

    // ---- merge + unscale (exact 2^-24) + dump C to smem ----
#pragma unroll
    for (int mt = 0; mt < 2; ++mt)
#pragma unroll
        for (int nt = 0; nt < 4; ++nt) {
            const int r0 = mbW + mt * 16 + g;
            const int c  = nhW + nt * 8 + 2 * t;
            *(float2*)&sf[r0 * CS + c] =
                make_float2((accM[mt][nt][0] + accC[mt][nt][0]) * INV_SC,
                            (accM[mt][nt][1] + accC[mt][nt][1]) * INV_SC);
            *(float2*)&sf[(r0 + 8) * CS + c] =
                make_float2((accM[mt][nt][2] + accC[mt][nt][2]) * INV_SC,
                            (accM[mt][nt][3] + accC[mt][nt][3]) * INV_SC);
        }
    __syncthreads();

    // ---- epilogue: thread tid<128 handles token tokBase+tid (validated) ----
    if (tid < MROWS) {
        const int tok = tokBase + tid;
        const float* pre = sf + tid * CS;
        const float* nzr = noise + (size_t)tok * E_FIX;

        float noisy[E_FIX];
#pragma unroll
        for (int q = 0; q < E_FIX / 4; ++q) {
            float4 lg = *(const float4*)(pre + 4 * q);
            float4 np = *(const float4*)(pre + E_FIX + 4 * q);
            float4 nv = *(const float4*)(nzr + 4 * q);
            float4 b0 = *(const float4*)(bl + 4 * q);
            float4 b1 = *(const float4*)(bn + 4 * q);
            noisy[4*q+0] = lg.x + b0.x + nv.x * softplus_f(np.x + b1.x);
            noisy[4*q+1] = lg.y + b0.y + nv.y * softplus_f(np.y + b1.y);
            noisy[4*q+2] = lg.z + b0.z + nv.z * softplus_f(np.z + b1.z);
            noisy[4*q+3] = lg.w + b0.w + nv.w * softplus_f(np.w + b1.w);
        }

        float m = noisy[0];
#pragma unroll
        for (int e = 1; e < E_FIX; ++e) m = fmaxf(m, noisy[e]);

        int kidx[8]; float kval[8];
        u64 chosen = 0ull;
        for (int j = 0; j < K; ++j) {
            float best = -INFINITY; int bi = 0;
#pragma unroll
            for (int e = 0; e < E_FIX; ++e) {
                bool ok = (((chosen >> e) & 1ull) == 0ull) && (noisy[e] > best);
                best = ok ? noisy[e] : best;
                bi   = ok ? e : bi;
            }
            kidx[j] = bi; kval[j] = best;
            chosen |= (1ull << bi);
        }

        float sum = 0.0f;
#pragma unroll
        for (int e = 0; e < E_FIX; ++e) { float x = expf(noisy[e] - m); noisy[e] = x; sum += x; }
        const float inv = 1.0f / sum;

        float* route = out + (size_t)tok * E_FIX;
        float* ixo   = out + (size_t)BS * E_FIX + (size_t)tok * K;
        float* fullp = out + (size_t)BS * (E_FIX + K) + (size_t)tok * E_FIX;
#pragma unroll
        for (int q = 0; q < 16; ++q) *(float4*)(route + 4 * q) = make_float4(0.f, 0.f, 0.f, 0.f);
#pragma unroll
        for (int q = 0; q < 16; ++q)
            *(float4*)(fullp + 4 * q) = make_float4(noisy[4*q+0] * inv, noisy[4*q+1] * inv,
                                                    noisy[4*q+2] * inv, noisy[4*q+3] * inv);
        const float rm = kval[0];
        float rs = 0.0f, rv[8];
        for (int j = 0; j < K; ++j) { rv[j] = expf(kval[j] - rm); rs += rv[j]; }
        const float rinv = 1.0f / rs;
        for (int j = 0; j < K; ++j) { route[kidx[j]] = rv[j] * rinv; ixo[j] = (float)kidx[j]; }
    }
}

// ----------------------------------------------------------------------------
// Inputs (metadata order): h, Wl, bl, Wn, bn, noise, [top_k]
// ----------------------------------------------------------------------------
extern "C" void kernel_launch(void* const* d_in, const int* in_sizes, int n_in,
                              void* d_out, int out_size) {
    const float* h  = (const float*)d_in[0];
    const float* Wl = (const float*)d_in[1];
    const float* bl = (const float*)d_in[2];
    const float* Wn = (const float*)d_in[3];
    const float* bn = (const float*)d_in[4];
    const float* nz = (const float*)d_in[5];

    const int E = in_sizes[2];                     // 64
    const int D = in_sizes[1] / E;                 // 1024
    const long long BSE = (long long)in_sizes[5];  // B*S*E
    const int BS = (int)(BSE / E);                 // 32768

    int K = (int)(((long long)out_size - 2LL * BSE) / (long long)BS);
    if (K < 1 || K > 8) K = 2;

    bsplit_kernel<<<128, 512>>>(Wl, Wn, D);
    cudaFuncSetAttribute(router_fused, cudaFuncAttributeMaxDynamicSharedMemorySize, SMEM_BYTES);
    router_fused<<<BS / MROWS, NTHR, SMEM_BYTES>>>(h, bl, bn, nz, (float*)d_out, D, BS, K);
}